// round 13
// baseline (speedup 1.0000x reference)
#include <cuda_runtime.h>
#include <math.h>
#include <stdint.h>

#define NB 65536
#define DIN 64
#define HH 512
#define LL 64
#define NCC 8
#define CODES 256

// ---------------- scratch (device globals; no allocation) ----------------
__device__ float  g_hact[(size_t)NB*HH];   // 128 MB
__device__ float  g_feat[(size_t)NB*HH];   // 128 MB
__device__ float  g_vs[(size_t)NB*72];     // 18 MB : [v(64) | raw scores(8)]
__device__ int    g_idx[NB*NCC];           // 2 MB
__device__ float  g_M[HH*NCC];             // Wk @ chart_q^T
__device__ float  g_m0[NCC];               // bk . chart_q
__device__ float  g_cbn[NCC*CODES];        // codebook row norms^2 (fp32, frozen)
__device__ double g_loss;

// ---------------- output layout (float32, tuple order concat) -------------
static const size_t OFF_KCHART = 0;
static const size_t OFF_KCODE  = (size_t)NB;
static const size_t OFF_ZN     = (size_t)2*NB;
static const size_t OFF_ZTEX   = (size_t)2*NB + (size_t)64*NB;
static const size_t OFF_ROUTER = (size_t)2*NB + (size_t)128*NB;
static const size_t OFF_ZGEO   = (size_t)2*NB + (size_t)128*NB + (size_t)8*NB;
static const size_t OFF_LOSS   = (size_t)202*NB;
static const size_t OFF_IDX    = (size_t)202*NB + 1;
static const size_t OFF_ZNALL  = (size_t)210*NB + 1;

__device__ __forceinline__ float gelu_exact_d(double x){
    return (float)(0.5*x*(1.0 + erf(x*0.70710678118654752440)));
}

// ---- packed f32x2 helpers (each lane is an exact fma.rn.f32) --------------
__device__ __forceinline__ unsigned long long pk2(float lo, float hi){
    unsigned long long r;
    asm("mov.b64 %0, {%1, %2};" : "=l"(r) : "f"(lo), "f"(hi));
    return r;
}
__device__ __forceinline__ void upk2(unsigned long long p, float& lo, float& hi){
    asm("mov.b64 {%0, %1}, %2;" : "=f"(lo), "=f"(hi) : "l"(p));
}
__device__ __forceinline__ unsigned long long ffma2(
        unsigned long long a, unsigned long long b, unsigned long long c){
    unsigned long long d;
    asm("fma.rn.f32x2 %0, %1, %2, %3;" : "=l"(d) : "l"(a), "l"(b), "l"(c));
    return d;
}

// ---------------- K0: prep (loss=0, M, m0, codebook norms) ----------------
__global__ void __launch_bounds__(256) k0_prep(
        const float* __restrict__ Wk, const float* __restrict__ bk,
        const float* __restrict__ cq, const float* __restrict__ cb){
    int t = blockIdx.x*256 + threadIdx.x;
    if (t == 0) g_loss = 0.0;
    if (t < HH*NCC){                         // M[i,c] = sum_j Wk[i,j]*cq[c,j]
        int i = t >> 3, c = t & 7;
        double s = 0.0;
        const float* wr = &Wk[(size_t)i*HH];
        const float* qr = &cq[(size_t)c*HH];
        for (int j = 0; j < HH; j++) s += (double)wr[j]*(double)qr[j];
        g_M[i*NCC + c] = (float)s;
    } else if (t < HH*NCC + NCC){            // m0[c] = bk . cq[c]
        int c = t - HH*NCC;
        double s = 0.0;
        const float* qr = &cq[(size_t)c*HH];
        for (int j = 0; j < HH; j++) s += (double)bk[j]*(double)qr[j];
        g_m0[c] = (float)s;
    } else if (t < HH*NCC + NCC + NCC*CODES){// ||codebook row||^2 (fp32, frozen)
        int e = t - (HH*NCC + NCC);
        float s = 0.f;
        const float* r = &cb[(size_t)e*LL];
        for (int l = 0; l < LL; l++) s += r[l]*r[l];
        g_cbn[e] = s;
    }
}

// ---- LN+gelu tail for one row (frozen math, hi-precision) -----------------
__device__ __forceinline__ void ln_gelu_row(
        const double* hd, const float* sb1, const float* slg,
        const float* slb, int lane, size_t rb){
    float hF[16];
    #pragma unroll
    for (int i = 0; i < 16; i++) hF[i] = (float)(hd[i] + (double)sb1[lane + 32*i]);
    double s = 0.0;
    #pragma unroll
    for (int i = 0; i < 16; i++) s += (double)hF[i];
    #pragma unroll
    for (int o = 16; o > 0; o >>= 1) s += __shfl_xor_sync(0xffffffffu, s, o);
    double mu = s * (1.0/512.0);
    double s2 = 0.0;
    #pragma unroll
    for (int i = 0; i < 16; i++){ double d = (double)hF[i] - mu; s2 += d*d; }
    #pragma unroll
    for (int o = 16; o > 0; o >>= 1) s2 += __shfl_xor_sync(0xffffffffu, s2, o);
    double var = s2 * (1.0/512.0);
    double rstd = 1.0/sqrt(var + 1e-5);
    #pragma unroll
    for (int i = 0; i < 16; i++){
        int j = lane + 32*i;
        double t = ((double)hF[i] - mu)*rstd*(double)slg[j] + (double)slb[j];
        g_hact[rb + j] = gelu_exact_d(t);
    }
}

// ---------------- K1: x@W1 (+b1) -> LN -> gelu; smem-staged W1, 2 rows/warp
__global__ void __launch_bounds__(256) k1_in(
        const float* __restrict__ x, const float* __restrict__ W1,
        const float* __restrict__ b1, const float* __restrict__ lg,
        const float* __restrict__ lb){
    __shared__ float xs[16][64];      // 4 KB
    __shared__ float w1s[16*HH];      // 32 KB (one k-chunk of W1)
    __shared__ float sb1[HH], slg[HH], slb[HH];  // 6 KB
    int b0 = blockIdx.x*16;
    int tid = threadIdx.x;
    {   // stage x rows + biases
        *(float4*)&xs[0][tid*4] = *(const float4*)&x[(size_t)b0*64 + tid*4];
        if (tid < 128){
            *(float4*)&sb1[tid*4] = *(const float4*)&b1[tid*4];
            *(float4*)&slg[tid*4] = *(const float4*)&lg[tid*4];
            *(float4*)&slb[tid*4] = *(const float4*)&lb[tid*4];
        }
    }
    int w = tid >> 5, lane = tid & 31;
    int r0 = w, r1 = w + 8;
    double hd0[16], hd1[16];
    #pragma unroll
    for (int i = 0; i < 16; i++){ hd0[i] = 0.0; hd1[i] = 0.0; }
    for (int kt = 0; kt < 4; kt++){
        __syncthreads();
        for (int i = tid; i < 2048; i += 256)
            *(float4*)&w1s[i*4] = *(const float4*)&W1[(size_t)kt*16*HH + i*4];
        __syncthreads();
        float hf0[16], hf1[16];
        #pragma unroll
        for (int i = 0; i < 16; i++){ hf0[i] = 0.f; hf1[i] = 0.f; }
        #pragma unroll
        for (int kk = 0; kk < 16; kk++){
            float xv0 = xs[r0][kt*16 + kk];
            float xv1 = xs[r1][kt*16 + kk];
            const float* wr = &w1s[kk*HH + lane];
            #pragma unroll
            for (int i = 0; i < 16; i++){
                float wv = wr[32*i];
                hf0[i] += xv0 * wv;      // frozen: same kk order as before
                hf1[i] += xv1 * wv;
            }
        }
        #pragma unroll
        for (int i = 0; i < 16; i++){ hd0[i] += (double)hf0[i]; hd1[i] += (double)hf1[i]; }
    }
    ln_gelu_row(hd0, sb1, slg, slb, lane, (size_t)(b0 + r0)*HH);
    ln_gelu_row(hd1, sb1, slg, slb, lane, (size_t)(b0 + r1)*HH);
}

// ---------------- K2: feat = gelu(hact@W2 + b2), f32x2 + dbl fold ---------
__global__ void __launch_bounds__(256) k2_gemm_gelu(
        const float* __restrict__ W2, const float* __restrict__ b2){
    __shared__ float As[16][136];
    __shared__ float Bs[16][72];
    int tid = threadIdx.x;
    int m0 = blockIdx.y*128, n0 = blockIdx.x*64;
    int tx = tid & 7, ty = tid >> 3;
    double accd[4][8];
    #pragma unroll
    for (int i = 0; i < 4; i++)
        #pragma unroll
        for (int j = 0; j < 8; j++) accd[i][j] = 0.0;
    for (int k0 = 0; k0 < HH; k0 += 16){
        #pragma unroll
        for (int i = 0; i < 2; i++){
            int pos = tid + i*256;
            int row = pos >> 2, kq = (pos & 3)*4;
            float4 va = *(const float4*)&g_hact[(size_t)(m0+row)*HH + k0 + kq];
            As[kq+0][row] = va.x; As[kq+1][row] = va.y;
            As[kq+2][row] = va.z; As[kq+3][row] = va.w;
        }
        {
            int kk = tid >> 4, nq = (tid & 15)*4;
            *(float4*)&Bs[kk][nq] = *(const float4*)&W2[(size_t)(k0+kk)*HH + n0 + nq];
        }
        __syncthreads();
        unsigned long long acc2[4][4];   // packed j-pairs; lanes = exact fma.rn chains
        #pragma unroll
        for (int i = 0; i < 4; i++)
            #pragma unroll
            for (int jp = 0; jp < 4; jp++) acc2[i][jp] = 0ULL;
        #pragma unroll
        for (int kk = 0; kk < 16; kk++){
            float4 a4 = *(const float4*)&As[kk][ty*4];
            ulonglong2 bp0 = *(const ulonglong2*)&Bs[kk][tx*8];
            ulonglong2 bp1 = *(const ulonglong2*)&Bs[kk][tx*8 + 4];
            float ar[4] = {a4.x, a4.y, a4.z, a4.w};
            #pragma unroll
            for (int i = 0; i < 4; i++){
                unsigned long long aa = pk2(ar[i], ar[i]);
                acc2[i][0] = ffma2(aa, bp0.x, acc2[i][0]);
                acc2[i][1] = ffma2(aa, bp0.y, acc2[i][1]);
                acc2[i][2] = ffma2(aa, bp1.x, acc2[i][2]);
                acc2[i][3] = ffma2(aa, bp1.y, acc2[i][3]);
            }
        }
        #pragma unroll
        for (int i = 0; i < 4; i++)
            #pragma unroll
            for (int jp = 0; jp < 4; jp++){
                float f0, f1;
                upk2(acc2[i][jp], f0, f1);
                accd[i][2*jp]   += (double)f0;   // same fold order as before
                accd[i][2*jp+1] += (double)f1;
            }
        __syncthreads();
    }
    #pragma unroll
    for (int i = 0; i < 4; i++){
        int gr = m0 + ty*4 + i;
        #pragma unroll
        for (int j = 0; j < 8; j++){
            int gc = n0 + tx*8 + j;
            double xv = accd[i][j] + (double)b2[gc];
            g_feat[(size_t)gr*HH + gc] = gelu_exact_d(xv);
        }
    }
}

// ---------------- K3: [v | raw scores] = feat @ [Wv | M], dbl-folded ------
__global__ void __launch_bounds__(256) k3_vproj(
        const float* __restrict__ Wv, const float* __restrict__ bv){
    __shared__ float Fs[64][33];
    __shared__ float Ws[32][72];
    int tid = threadIdx.x;
    int b0 = blockIdx.x*64;
    int rr = tid & 31;           // rows rr and rr+32
    int cg = (tid >> 5)*9;       // 9 cols
    double accd[2][9];
    #pragma unroll
    for (int i = 0; i < 2; i++)
        #pragma unroll
        for (int j = 0; j < 9; j++) accd[i][j] = 0.0;
    for (int k0 = 0; k0 < HH; k0 += 32){
        #pragma unroll
        for (int i = 0; i < 2; i++){
            int pos = tid + i*256;            // 512 float4s = 64 rows x 8
            int r = pos >> 3, q = pos & 7;
            float4 f4 = *(const float4*)&g_feat[(size_t)(b0+r)*HH + k0 + q*4];
            Fs[r][q*4+0] = f4.x; Fs[r][q*4+1] = f4.y;
            Fs[r][q*4+2] = f4.z; Fs[r][q*4+3] = f4.w;
        }
        #pragma unroll
        for (int i = 0; i < 9; i++){
            int pos = tid + i*256;            // 2304 = 32x72
            if (pos < 32*72){
                int kk = pos/72, c = pos%72;
                Ws[kk][c] = (c < 64) ? Wv[(size_t)(k0+kk)*LL + c]
                                     : g_M[(size_t)(k0+kk)*NCC + (c-64)];
            }
        }
        __syncthreads();
        float acc[2][9];
        #pragma unroll
        for (int i = 0; i < 2; i++)
            #pragma unroll
            for (int j = 0; j < 9; j++) acc[i][j] = 0.f;
        #pragma unroll
        for (int kk = 0; kk < 32; kk++){
            float a0 = Fs[rr][kk], a1 = Fs[rr+32][kk];
            #pragma unroll
            for (int j = 0; j < 9; j++){
                float wv = Ws[kk][cg + j];
                acc[0][j] += a0*wv;
                acc[1][j] += a1*wv;
            }
        }
        #pragma unroll
        for (int i = 0; i < 2; i++)
            #pragma unroll
            for (int j = 0; j < 9; j++) accd[i][j] += (double)acc[i][j];
        __syncthreads();
    }
    #pragma unroll
    for (int ii = 0; ii < 2; ii++){
        size_t rb = (size_t)(b0 + rr + ii*32)*72;
        #pragma unroll
        for (int j = 0; j < 9; j++){
            int c = cg + j;
            double bias = (c < 64) ? (double)bv[c] : 0.0;
            g_vs[rb + c] = (float)(accd[ii][j] + bias);
        }
    }
}

// ---------------- K4: softmax router + K_chart ----------------------------
__global__ void __launch_bounds__(256) k4_router(float* __restrict__ out){
    int b = blockIdx.x*256 + threadIdx.x;
    const float rs = 0.04419417382415922f;   // 1/sqrt(512)
    float s[8];
    float mx = -INFINITY; int am = 0;
    #pragma unroll
    for (int c = 0; c < 8; c++){
        float v = (g_vs[(size_t)b*72 + 64 + c] + g_m0[c]) * rs;
        s[c] = v;
        if (v > mx){ mx = v; am = c; }       // first max wins
    }
    float se = 0.f;
    #pragma unroll
    for (int c = 0; c < 8; c++){ s[c] = expf(s[c] - mx); se += s[c]; }
    float inv = 1.0f/se;
    #pragma unroll
    for (int c = 0; c < 8; c++) out[OFF_ROUTER + (size_t)b*8 + c] = s[c]*inv;
    out[OFF_KCHART + b] = (float)am;
}

// ---------------- K5: VQ argmin — code-in-register, transposed-v, f32x2 ---
// One code per thread; v stored transposed so row-pairs load as 64-bit lanes.
// Each dot is still the frozen sequential l=0..63 fma.rn chain.
__global__ void __launch_bounds__(256, 2) k5_vq(
        const float* __restrict__ cb, float* __restrict__ out){
    __shared__ float s_buf[128*68];  // 34.8 KB: code staging / d matrix (reuse)
    __shared__ float s_vT[64*36];    // 9 KB: v transposed, stride 36 (16B quads)
    __shared__ float s_v2[32];
    __shared__ float s_bd[32][8];
    __shared__ int   s_bi[32][8];
    int b0 = blockIdx.x*32;
    int tid = threadIdx.x;
    int row8 = tid >> 3, t8 = tid & 7;
    // stage v transposed: s_vT[l*36 + r] = v[r][l]
    for (int i = tid; i < 2048; i += 256){
        int r = i >> 6, l = i & 63;
        s_vT[l*36 + r] = g_vs[(size_t)(b0 + r)*72 + l];
    }
    __syncthreads();
    if (tid < 32){                           // v2: frozen sequential l=0..63
        float v2 = 0.f;
        for (int l = 0; l < 64; l++){ float xv = s_vT[l*36 + tid]; v2 += xv*xv; }
        s_v2[tid] = v2;
    }
    int myidx[NCC];
    float code[64];
    for (int n = 0; n < NCC; n++){
        __syncthreads();                     // prior d-matrix reads done
        for (int i = tid; i < 128*16; i += 256){   // stage codes 0..127
            int r = i >> 4, q = i & 15;
            *(float4*)&s_buf[r*68 + q*4] =
                *(const float4*)&cb[((size_t)n*CODES + r)*64 + q*4];
        }
        __syncthreads();
        if (tid < 128){
            #pragma unroll
            for (int q = 0; q < 16; q++){
                float4 c4 = *(const float4*)&s_buf[tid*68 + q*4];
                code[q*4+0] = c4.x; code[q*4+1] = c4.y;
                code[q*4+2] = c4.z; code[q*4+3] = c4.w;
            }
        }
        __syncthreads();
        for (int i = tid; i < 128*16; i += 256){   // stage codes 128..255
            int r = i >> 4, q = i & 15;
            *(float4*)&s_buf[r*68 + q*4] =
                *(const float4*)&cb[((size_t)n*CODES + 128 + r)*64 + q*4];
        }
        __syncthreads();
        if (tid >= 128){
            int tr = tid - 128;
            #pragma unroll
            for (int q = 0; q < 16; q++){
                float4 c4 = *(const float4*)&s_buf[tr*68 + q*4];
                code[q*4+0] = c4.x; code[q*4+1] = c4.y;
                code[q*4+2] = c4.z; code[q*4+3] = c4.w;
            }
        }
        float mycbn = g_cbn[n*CODES + tid];
        __syncthreads();                     // reg loads done; s_buf -> d matrix
        #pragma unroll 1
        for (int rq = 0; rq < 8; rq++){      // 4 rows per sweep
            unsigned long long d2a = 0ULL, d2b = 0ULL;
            #pragma unroll
            for (int l = 0; l < 64; l++){
                ulonglong2 vp = *(const ulonglong2*)&s_vT[l*36 + rq*4]; // broadcast
                unsigned long long cc = pk2(code[l], code[l]);
                d2a = ffma2(cc, vp.x, d2a);  // rows rq*4, rq*4+1
                d2b = ffma2(cc, vp.y, d2b);  // rows rq*4+2, rq*4+3
            }
            float dr0, dr1, dr2, dr3;
            upk2(d2a, dr0, dr1); upk2(d2b, dr2, dr3);
            int r = rq*4;
            s_buf[(r+0)*264 + tid] = (s_v2[r+0] + mycbn) - 2.0f*dr0;  // frozen
            s_buf[(r+1)*264 + tid] = (s_v2[r+1] + mycbn) - 2.0f*dr1;
            s_buf[(r+2)*264 + tid] = (s_v2[r+2] + mycbn) - 2.0f*dr2;
            s_buf[(r+3)*264 + tid] = (s_v2[r+3] + mycbn) - 2.0f*dr3;
        }
        __syncthreads();
        {   // partial argmin: 8 threads/row, interleaved codes, index tie-break
            float bd = INFINITY; int bi = 0x7fffffff;
            #pragma unroll 1
            for (int k = 0; k < 32; k++){
                int c = (k << 3) + t8;
                float d = s_buf[row8*264 + c];
                if (d < bd || (d == bd && c < bi)){ bd = d; bi = c; }
            }
            s_bd[row8][t8] = bd; s_bi[row8][t8] = bi;
        }
        __syncthreads();
        if (t8 == 0){
            float best = s_bd[row8][0]; int besti = s_bi[row8][0];
            for (int q = 1; q < 8; q++){
                float dq = s_bd[row8][q]; int iq = s_bi[row8][q];
                if (dq < best || (dq == best && iq < besti)){ best = dq; besti = iq; }
            }
            int b = b0 + row8;
            g_idx[b*NCC + n] = besti;
            out[OFF_IDX + (size_t)b*NCC + n] = (float)besti;
            myidx[n] = besti;
        }
    }
    if (t8 == 0){
        int b = b0 + row8;
        int kc = (int)lrintf(out[OFF_KCHART + b]);
        out[OFF_KCODE + b] = (float)myidx[kc];
    }
}

// ---------------- K6: refinement MLP, blends, loss — 8 b per block --------
__global__ void __launch_bounds__(256) k6_final(
        const float* __restrict__ cb,  const float* __restrict__ Ws1,
        const float* __restrict__ bs1, const float* __restrict__ Ws2,
        const float* __restrict__ bs2, float* __restrict__ out){
    __shared__ float sW1[2048];
    __shared__ float sW2[2048];
    __shared__ float sb1[32];
    __shared__ float sb2[64];
    __shared__ float sloss[8];
    int tid = threadIdx.x;
    int w = tid >> 5, lane = tid & 31;
    for (int i = tid; i < 512; i += 256){
        *(float4*)&sW1[i*4] = *(const float4*)&Ws1[i*4];
        *(float4*)&sW2[i*4] = *(const float4*)&Ws2[i*4];
    }
    if (tid < 32) sb1[tid] = bs1[tid];
    else if (tid < 96) sb2[tid - 32] = bs2[tid - 32];
    __syncthreads();

    int b = blockIdx.x*8 + w;
    float v0 = g_vs[(size_t)b*72 + lane];
    float v1 = g_vs[(size_t)b*72 + lane + 32];
    float rln = (lane < 8) ? out[OFF_ROUTER + (size_t)b*8 + lane] : 0.f;
    float zn0 = 0.f, zn1 = 0.f, zq0 = 0.f, zq1 = 0.f, lacc = 0.f;

    #pragma unroll 1
    for (int n = 0; n < NCC; n++){
        int idx = g_idx[b*NCC + n];
        const float* cr = &cb[((size_t)n*CODES + idx)*64];
        float z0 = cr[lane], z1 = cr[lane + 32];
        float d0 = v0 - z0, d1 = v1 - z1;

        float hid = sb1[lane];
        #pragma unroll
        for (int k = 0; k < 32; k++){
            float dk = __shfl_sync(0xffffffffu, d0, k);
            hid += dk * sW1[k*32 + lane];
        }
        #pragma unroll
        for (int k = 0; k < 32; k++){
            float dk = __shfl_sync(0xffffffffu, d1, k);
            hid += dk * sW1[(k + 32)*32 + lane];
        }
        float gg = 0.5f*hid*(1.0f + erff(hid*0.70710678f));
        float o0 = sb2[lane], o1 = sb2[lane + 32];
        #pragma unroll
        for (int k = 0; k < 32; k++){
            float hk = __shfl_sync(0xffffffffu, gg, k);
            o0 += hk * sW2[k*64 + lane];
            o1 += hk * sW2[k*64 + lane + 32];
        }
        size_t zb = OFF_ZNALL + ((size_t)b*NCC + n)*64;
        out[zb + lane]      = o0;
        out[zb + lane + 32] = o1;

        float rw = __shfl_sync(0xffffffffu, rln, n);
        zn0 += rw*o0; zn1 += rw*o1;          // deterministic n-ascending sum
        zq0 += rw*z0; zq1 += rw*z1;

        float dd = d0*d0 + d1*d1;
        #pragma unroll
        for (int o = 16; o > 0; o >>= 1) dd += __shfl_xor_sync(0xffffffffu, dd, o);
        lacc += rw*dd;
    }

    out[OFF_ZN   + (size_t)b*64 + lane]      = zn0;
    out[OFF_ZN   + (size_t)b*64 + lane + 32] = zn1;
    out[OFF_ZTEX + (size_t)b*64 + lane]      = v0 - zq0 - zn0;
    out[OFF_ZTEX + (size_t)b*64 + lane + 32] = v1 - zq1 - zn1;
    out[OFF_ZGEO + (size_t)b*64 + lane]      = zq0 + zn0;
    out[OFF_ZGEO + (size_t)b*64 + lane + 32] = zq1 + zn1;

    if (lane == 0) sloss[w] = lacc;
    __syncthreads();
    if (tid == 0){
        float s = 0.f;
        #pragma unroll
        for (int i = 0; i < 8; i++) s += sloss[i];
        atomicAdd(&g_loss, (double)s);
    }
}

// ---------------- K7: vq_loss = 1.25 * S / (B*L) --------------------------
__global__ void k7_loss(float* __restrict__ out){
    out[OFF_LOSS] = (float)(1.25 * g_loss / ((double)NB * (double)LL));
}

// ---------------- launch ---------------------------------------------------
extern "C" void kernel_launch(void* const* d_in, const int* in_sizes, int n_in,
                              void* d_out, int out_size){
    const float* x   = (const float*)d_in[0];
    const float* W1  = (const float*)d_in[1];
    const float* b1  = (const float*)d_in[2];
    const float* lg  = (const float*)d_in[3];
    const float* lb  = (const float*)d_in[4];
    const float* W2  = (const float*)d_in[5];
    const float* b2  = (const float*)d_in[6];
    const float* Wk  = (const float*)d_in[7];
    const float* bk  = (const float*)d_in[8];
    const float* cq  = (const float*)d_in[9];
    const float* Wv  = (const float*)d_in[10];
    const float* bv  = (const float*)d_in[11];
    const float* cb  = (const float*)d_in[12];
    const float* Ws1 = (const float*)d_in[13];
    const float* bs1 = (const float*)d_in[14];
    const float* Ws2 = (const float*)d_in[15];
    const float* bs2 = (const float*)d_in[16];
    float* out = (float*)d_out;

    k0_prep<<<25, 256>>>(Wk, bk, cq, cb);
    k1_in<<<NB/16, 256>>>(x, W1, b1, lg, lb);
    dim3 g2(HH/64, NB/128);
    k2_gemm_gelu<<<g2, 256>>>(W2, b2);
    k3_vproj<<<NB/64, 256>>>(Wv, bv);
    k4_router<<<NB/256, 256>>>(out);
    k5_vq<<<NB/32, 256>>>(cb, out);
    k6_final<<<NB/8, 256>>>(cb, Ws1, bs1, Ws2, bs2, out);
    k7_loss<<<1, 1>>>(out);
}

// round 14
// speedup vs baseline: 1.1388x; 1.1388x over previous
#include <cuda_runtime.h>
#include <math.h>
#include <stdint.h>

#define NB 65536
#define DIN 64
#define HH 512
#define LL 64
#define NCC 8
#define CODES 256

// ---------------- scratch (device globals; no allocation) ----------------
__device__ float  g_hact[(size_t)NB*HH];   // 128 MB
__device__ float  g_feat[(size_t)NB*HH];   // 128 MB
__device__ float  g_vs[(size_t)NB*72];     // 18 MB : [v(64) | raw scores(8)]
__device__ int    g_idx[NB*NCC];           // 2 MB
__device__ float  g_M[HH*NCC];             // Wk @ chart_q^T
__device__ float  g_m0[NCC];               // bk . chart_q
__device__ float  g_cbn[NCC*CODES];        // codebook row norms^2 (fp32, frozen)
__device__ double g_loss;

// ---------------- output layout (float32, tuple order concat) -------------
static const size_t OFF_KCHART = 0;
static const size_t OFF_KCODE  = (size_t)NB;
static const size_t OFF_ZN     = (size_t)2*NB;
static const size_t OFF_ZTEX   = (size_t)2*NB + (size_t)64*NB;
static const size_t OFF_ROUTER = (size_t)2*NB + (size_t)128*NB;
static const size_t OFF_ZGEO   = (size_t)2*NB + (size_t)128*NB + (size_t)8*NB;
static const size_t OFF_LOSS   = (size_t)202*NB;
static const size_t OFF_IDX    = (size_t)202*NB + 1;
static const size_t OFF_ZNALL  = (size_t)210*NB + 1;

__device__ __forceinline__ float gelu_exact_d(double x){
    return (float)(0.5*x*(1.0 + erf(x*0.70710678118654752440)));
}

// ---------------- K0: prep (loss=0, M, m0, codebook norms) ----------------
__global__ void __launch_bounds__(256) k0_prep(
        const float* __restrict__ Wk, const float* __restrict__ bk,
        const float* __restrict__ cq, const float* __restrict__ cb){
    int t = blockIdx.x*256 + threadIdx.x;
    if (t == 0) g_loss = 0.0;
    if (t < HH*NCC){                         // M[i,c] = sum_j Wk[i,j]*cq[c,j]
        int i = t >> 3, c = t & 7;
        double s = 0.0;
        const float* wr = &Wk[(size_t)i*HH];
        const float* qr = &cq[(size_t)c*HH];
        for (int j = 0; j < HH; j++) s += (double)wr[j]*(double)qr[j];
        g_M[i*NCC + c] = (float)s;
    } else if (t < HH*NCC + NCC){            // m0[c] = bk . cq[c]
        int c = t - HH*NCC;
        double s = 0.0;
        const float* qr = &cq[(size_t)c*HH];
        for (int j = 0; j < HH; j++) s += (double)bk[j]*(double)qr[j];
        g_m0[c] = (float)s;
    } else if (t < HH*NCC + NCC + NCC*CODES){// ||codebook row||^2 (fp32, frozen)
        int e = t - (HH*NCC + NCC);
        float s = 0.f;
        const float* r = &cb[(size_t)e*LL];
        for (int l = 0; l < LL; l++) s += r[l]*r[l];
        g_cbn[e] = s;
    }
}

// ---- LN+gelu tail for one row (frozen math, hi-precision) -----------------
__device__ __forceinline__ void ln_gelu_row(
        const double* hd, const float* sb1, const float* slg,
        const float* slb, int lane, size_t rb){
    float hF[16];
    #pragma unroll
    for (int i = 0; i < 16; i++) hF[i] = (float)(hd[i] + (double)sb1[lane + 32*i]);
    double s = 0.0;
    #pragma unroll
    for (int i = 0; i < 16; i++) s += (double)hF[i];
    #pragma unroll
    for (int o = 16; o > 0; o >>= 1) s += __shfl_xor_sync(0xffffffffu, s, o);
    double mu = s * (1.0/512.0);
    double s2 = 0.0;
    #pragma unroll
    for (int i = 0; i < 16; i++){ double d = (double)hF[i] - mu; s2 += d*d; }
    #pragma unroll
    for (int o = 16; o > 0; o >>= 1) s2 += __shfl_xor_sync(0xffffffffu, s2, o);
    double var = s2 * (1.0/512.0);
    double rstd = 1.0/sqrt(var + 1e-5);
    #pragma unroll
    for (int i = 0; i < 16; i++){
        int j = lane + 32*i;
        double t = ((double)hF[i] - mu)*rstd*(double)slg[j] + (double)slb[j];
        g_hact[rb + j] = gelu_exact_d(t);
    }
}

// ---------------- K1: x@W1 (+b1) -> LN -> gelu; smem-staged W1, 2 rows/warp
__global__ void __launch_bounds__(256) k1_in(
        const float* __restrict__ x, const float* __restrict__ W1,
        const float* __restrict__ b1, const float* __restrict__ lg,
        const float* __restrict__ lb){
    __shared__ float xs[16][64];      // 4 KB
    __shared__ float w1s[16*HH];      // 32 KB (one k-chunk of W1)
    __shared__ float sb1[HH], slg[HH], slb[HH];  // 6 KB
    int b0 = blockIdx.x*16;
    int tid = threadIdx.x;
    {   // stage x rows + biases
        *(float4*)&xs[0][tid*4] = *(const float4*)&x[(size_t)b0*64 + tid*4];
        if (tid < 128){
            *(float4*)&sb1[tid*4] = *(const float4*)&b1[tid*4];
            *(float4*)&slg[tid*4] = *(const float4*)&lg[tid*4];
            *(float4*)&slb[tid*4] = *(const float4*)&lb[tid*4];
        }
    }
    int w = tid >> 5, lane = tid & 31;
    int r0 = w, r1 = w + 8;
    double hd0[16], hd1[16];
    #pragma unroll
    for (int i = 0; i < 16; i++){ hd0[i] = 0.0; hd1[i] = 0.0; }
    for (int kt = 0; kt < 4; kt++){
        __syncthreads();
        for (int i = tid; i < 2048; i += 256)
            *(float4*)&w1s[i*4] = *(const float4*)&W1[(size_t)kt*16*HH + i*4];
        __syncthreads();
        float hf0[16], hf1[16];
        #pragma unroll
        for (int i = 0; i < 16; i++){ hf0[i] = 0.f; hf1[i] = 0.f; }
        #pragma unroll
        for (int kk = 0; kk < 16; kk++){
            float xv0 = xs[r0][kt*16 + kk];
            float xv1 = xs[r1][kt*16 + kk];
            const float* wr = &w1s[kk*HH + lane];
            #pragma unroll
            for (int i = 0; i < 16; i++){
                float wv = wr[32*i];
                hf0[i] += xv0 * wv;      // frozen: same kk order as before
                hf1[i] += xv1 * wv;
            }
        }
        #pragma unroll
        for (int i = 0; i < 16; i++){ hd0[i] += (double)hf0[i]; hd1[i] += (double)hf1[i]; }
    }
    ln_gelu_row(hd0, sb1, slg, slb, lane, (size_t)(b0 + r0)*HH);
    ln_gelu_row(hd1, sb1, slg, slb, lane, (size_t)(b0 + r1)*HH);
}

// ---------------- K2: feat = gelu(hact@W2 + b2), double-buffered SGEMM ----
// FMA chains / fold order identical to the 3435us version; only load
// scheduling changed (prefetch + 2-buffer smem, one sync per k-tile).
__global__ void __launch_bounds__(256, 2) k2_gemm_gelu(
        const float* __restrict__ W2, const float* __restrict__ b2){
    __shared__ float As[2][16][136];   // 17.4 KB
    __shared__ float Bs[2][16][72];    // 9.2 KB
    int tid = threadIdx.x;
    int m0 = blockIdx.y*128, n0 = blockIdx.x*64;
    int tx = tid & 7, ty = tid >> 3;
    int ar0 = tid >> 2, akq = (tid & 3)*4;   // A: rows ar0, ar0+64
    int ar1 = ar0 + 64;
    int bkk = tid >> 4, bnq = (tid & 15)*4;  // B: one float4
    const float* aptr0 = &g_hact[(size_t)(m0+ar0)*HH + akq];
    const float* aptr1 = &g_hact[(size_t)(m0+ar1)*HH + akq];
    const float* bptr  = &W2[(size_t)bkk*HH + n0 + bnq];

    double accd[4][8];
    #pragma unroll
    for (int i = 0; i < 4; i++)
        #pragma unroll
        for (int j = 0; j < 8; j++) accd[i][j] = 0.0;

    // prologue: tile 0 -> buf 0
    float4 va0 = *(const float4*)aptr0;
    float4 va1 = *(const float4*)aptr1;
    float4 vb  = *(const float4*)bptr;
    As[0][akq+0][ar0] = va0.x; As[0][akq+1][ar0] = va0.y;
    As[0][akq+2][ar0] = va0.z; As[0][akq+3][ar0] = va0.w;
    As[0][akq+0][ar1] = va1.x; As[0][akq+1][ar1] = va1.y;
    As[0][akq+2][ar1] = va1.z; As[0][akq+3][ar1] = va1.w;
    *(float4*)&Bs[0][bkk][bnq] = vb;
    __syncthreads();

    for (int kt = 0; kt < 32; kt++){
        int buf = kt & 1;
        if (kt < 31){                         // prefetch next tile into regs
            va0 = *(const float4*)(aptr0 + (kt+1)*16);
            va1 = *(const float4*)(aptr1 + (kt+1)*16);
            vb  = *(const float4*)(bptr + (size_t)(kt+1)*16*HH);
        }
        float accf[4][8];
        #pragma unroll
        for (int i = 0; i < 4; i++)
            #pragma unroll
            for (int j = 0; j < 8; j++) accf[i][j] = 0.f;
        #pragma unroll
        for (int kk = 0; kk < 16; kk++){
            float4 a4  = *(const float4*)&As[buf][kk][ty*4];
            float4 b4a = *(const float4*)&Bs[buf][kk][tx*8];
            float4 b4b = *(const float4*)&Bs[buf][kk][tx*8 + 4];
            float ar[4] = {a4.x, a4.y, a4.z, a4.w};
            float br[8] = {b4a.x, b4a.y, b4a.z, b4a.w,
                           b4b.x, b4b.y, b4b.z, b4b.w};
            #pragma unroll
            for (int i = 0; i < 4; i++)
                #pragma unroll
                for (int j = 0; j < 8; j++) accf[i][j] += ar[i]*br[j];
        }
        #pragma unroll
        for (int i = 0; i < 4; i++)
            #pragma unroll
            for (int j = 0; j < 8; j++) accd[i][j] += (double)accf[i][j];
        if (kt < 31){                         // store prefetch -> other buffer
            int nb = buf ^ 1;
            As[nb][akq+0][ar0] = va0.x; As[nb][akq+1][ar0] = va0.y;
            As[nb][akq+2][ar0] = va0.z; As[nb][akq+3][ar0] = va0.w;
            As[nb][akq+0][ar1] = va1.x; As[nb][akq+1][ar1] = va1.y;
            As[nb][akq+2][ar1] = va1.z; As[nb][akq+3][ar1] = va1.w;
            *(float4*)&Bs[nb][bkk][bnq] = vb;
        }
        __syncthreads();
    }
    #pragma unroll
    for (int i = 0; i < 4; i++){
        int gr = m0 + ty*4 + i;
        #pragma unroll
        for (int j = 0; j < 8; j++){
            int gc = n0 + tx*8 + j;
            double xv = accd[i][j] + (double)b2[gc];
            g_feat[(size_t)gr*HH + gc] = gelu_exact_d(xv);
        }
    }
}

// ---------------- K3: [v | raw scores] = feat @ [Wv | M], dbl-folded ------
__global__ void __launch_bounds__(256) k3_vproj(
        const float* __restrict__ Wv, const float* __restrict__ bv){
    __shared__ float Fs[64][33];
    __shared__ float Ws[32][72];
    int tid = threadIdx.x;
    int b0 = blockIdx.x*64;
    int rr = tid & 31;           // rows rr and rr+32
    int cg = (tid >> 5)*9;       // 9 cols
    double accd[2][9];
    #pragma unroll
    for (int i = 0; i < 2; i++)
        #pragma unroll
        for (int j = 0; j < 9; j++) accd[i][j] = 0.0;
    for (int k0 = 0; k0 < HH; k0 += 32){
        #pragma unroll
        for (int i = 0; i < 2; i++){
            int pos = tid + i*256;            // 512 float4s = 64 rows x 8
            int r = pos >> 3, q = pos & 7;
            float4 f4 = *(const float4*)&g_feat[(size_t)(b0+r)*HH + k0 + q*4];
            Fs[r][q*4+0] = f4.x; Fs[r][q*4+1] = f4.y;
            Fs[r][q*4+2] = f4.z; Fs[r][q*4+3] = f4.w;
        }
        #pragma unroll
        for (int i = 0; i < 9; i++){
            int pos = tid + i*256;            // 2304 = 32x72
            if (pos < 32*72){
                int kk = pos/72, c = pos%72;
                Ws[kk][c] = (c < 64) ? Wv[(size_t)(k0+kk)*LL + c]
                                     : g_M[(size_t)(k0+kk)*NCC + (c-64)];
            }
        }
        __syncthreads();
        float acc[2][9];
        #pragma unroll
        for (int i = 0; i < 2; i++)
            #pragma unroll
            for (int j = 0; j < 9; j++) acc[i][j] = 0.f;
        #pragma unroll
        for (int kk = 0; kk < 32; kk++){
            float a0 = Fs[rr][kk], a1 = Fs[rr+32][kk];
            #pragma unroll
            for (int j = 0; j < 9; j++){
                float wv = Ws[kk][cg + j];
                acc[0][j] += a0*wv;
                acc[1][j] += a1*wv;
            }
        }
        #pragma unroll
        for (int i = 0; i < 2; i++)
            #pragma unroll
            for (int j = 0; j < 9; j++) accd[i][j] += (double)acc[i][j];
        __syncthreads();
    }
    #pragma unroll
    for (int ii = 0; ii < 2; ii++){
        size_t rb = (size_t)(b0 + rr + ii*32)*72;
        #pragma unroll
        for (int j = 0; j < 9; j++){
            int c = cg + j;
            double bias = (c < 64) ? (double)bv[c] : 0.0;
            g_vs[rb + c] = (float)(accd[ii][j] + bias);
        }
    }
}

// ---------------- K4: softmax router + K_chart ----------------------------
__global__ void __launch_bounds__(256) k4_router(float* __restrict__ out){
    int b = blockIdx.x*256 + threadIdx.x;
    const float rs = 0.04419417382415922f;   // 1/sqrt(512)
    float s[8];
    float mx = -INFINITY; int am = 0;
    #pragma unroll
    for (int c = 0; c < 8; c++){
        float v = (g_vs[(size_t)b*72 + 64 + c] + g_m0[c]) * rs;
        s[c] = v;
        if (v > mx){ mx = v; am = c; }       // first max wins
    }
    float se = 0.f;
    #pragma unroll
    for (int c = 0; c < 8; c++){ s[c] = expf(s[c] - mx); se += s[c]; }
    float inv = 1.0f/se;
    #pragma unroll
    for (int c = 0; c < 8; c++) out[OFF_ROUTER + (size_t)b*8 + c] = s[c]*inv;
    out[OFF_KCHART + b] = (float)am;
}

// ---------------- K5: VQ argmin — code-in-register, broadcast-v -----------
// One code per thread (256 = CODES); v read via uniform-address LDS
// (broadcast). All FMA chains / combine expr bit-identical.
__global__ void __launch_bounds__(256, 2) k5_vq(
        const float* __restrict__ cb, float* __restrict__ out){
    __shared__ float s_buf[128*68];  // 34.8 KB: code staging / d matrix (reuse)
    __shared__ float s_v[32*68];     // 8.7 KB
    __shared__ float s_v2[32];
    __shared__ float s_bd[32][8];
    __shared__ int   s_bi[32][8];
    int b0 = blockIdx.x*32;
    int tid = threadIdx.x;
    int row8 = tid >> 3, t8 = tid & 7;
    // stage v rows (32 x 16 float4)
    for (int i = tid; i < 512; i += 256){
        int r = i >> 4, q = i & 15;
        *(float4*)&s_v[r*68 + q*4] =
            *(const float4*)&g_vs[(size_t)(b0 + r)*72 + q*4];
    }
    __syncthreads();
    if (tid < 32){                           // v2: frozen sequential l=0..63
        float v2 = 0.f;
        for (int l = 0; l < 64; l++){ float xv = s_v[tid*68 + l]; v2 += xv*xv; }
        s_v2[tid] = v2;
    }
    int myidx[NCC];
    float code[64];
    for (int n = 0; n < NCC; n++){
        __syncthreads();                     // prior d-matrix reads done
        for (int i = tid; i < 128*16; i += 256){   // stage codes 0..127
            int r = i >> 4, q = i & 15;
            *(float4*)&s_buf[r*68 + q*4] =
                *(const float4*)&cb[((size_t)n*CODES + r)*64 + q*4];
        }
        __syncthreads();
        if (tid < 128){
            #pragma unroll
            for (int q = 0; q < 16; q++){
                float4 c4 = *(const float4*)&s_buf[tid*68 + q*4];
                code[q*4+0] = c4.x; code[q*4+1] = c4.y;
                code[q*4+2] = c4.z; code[q*4+3] = c4.w;
            }
        }
        __syncthreads();
        for (int i = tid; i < 128*16; i += 256){   // stage codes 128..255
            int r = i >> 4, q = i & 15;
            *(float4*)&s_buf[r*68 + q*4] =
                *(const float4*)&cb[((size_t)n*CODES + 128 + r)*64 + q*4];
        }
        __syncthreads();
        if (tid >= 128){
            int tr = tid - 128;
            #pragma unroll
            for (int q = 0; q < 16; q++){
                float4 c4 = *(const float4*)&s_buf[tr*68 + q*4];
                code[q*4+0] = c4.x; code[q*4+1] = c4.y;
                code[q*4+2] = c4.z; code[q*4+3] = c4.w;
            }
        }
        float mycbn = g_cbn[n*CODES + tid];
        __syncthreads();                     // reg loads done; s_buf -> d matrix
        #pragma unroll 1
        for (int r = 0; r < 32; r++){
            float dot = 0.f;                 // frozen l=0..63 chain
            #pragma unroll
            for (int q = 0; q < 16; q++){
                float4 v4 = *(const float4*)&s_v[r*68 + q*4];  // broadcast
                dot += code[q*4+0]*v4.x;
                dot += code[q*4+1]*v4.y;
                dot += code[q*4+2]*v4.z;
                dot += code[q*4+3]*v4.w;
            }
            float d = (s_v2[r] + mycbn) - 2.0f*dot;   // frozen combine
            s_buf[r*264 + tid] = d;          // consecutive -> conflict-free
        }
        __syncthreads();
        {   // partial argmin: 8 threads/row, interleaved codes, index tie-break
            float bd = INFINITY; int bi = 0x7fffffff;
            #pragma unroll 1
            for (int k = 0; k < 32; k++){
                int c = (k << 3) + t8;
                float d = s_buf[row8*264 + c];
                if (d < bd || (d == bd && c < bi)){ bd = d; bi = c; }
            }
            s_bd[row8][t8] = bd; s_bi[row8][t8] = bi;
        }
        __syncthreads();
        if (t8 == 0){
            float best = s_bd[row8][0]; int besti = s_bi[row8][0];
            for (int q = 1; q < 8; q++){
                float dq = s_bd[row8][q]; int iq = s_bi[row8][q];
                if (dq < best || (dq == best && iq < besti)){ best = dq; besti = iq; }
            }
            int b = b0 + row8;
            g_idx[b*NCC + n] = besti;
            out[OFF_IDX + (size_t)b*NCC + n] = (float)besti;
            myidx[n] = besti;
        }
    }
    if (t8 == 0){
        int b = b0 + row8;
        int kc = (int)lrintf(out[OFF_KCHART + b]);
        out[OFF_KCODE + b] = (float)myidx[kc];
    }
}

// ---------------- K6: refinement MLP, blends, loss — 8 b per block --------
__global__ void __launch_bounds__(256) k6_final(
        const float* __restrict__ cb,  const float* __restrict__ Ws1,
        const float* __restrict__ bs1, const float* __restrict__ Ws2,
        const float* __restrict__ bs2, float* __restrict__ out){
    __shared__ float sW1[2048];
    __shared__ float sW2[2048];
    __shared__ float sb1[32];
    __shared__ float sb2[64];
    __shared__ float sloss[8];
    int tid = threadIdx.x;
    int w = tid >> 5, lane = tid & 31;
    for (int i = tid; i < 512; i += 256){
        *(float4*)&sW1[i*4] = *(const float4*)&Ws1[i*4];
        *(float4*)&sW2[i*4] = *(const float4*)&Ws2[i*4];
    }
    if (tid < 32) sb1[tid] = bs1[tid];
    else if (tid < 96) sb2[tid - 32] = bs2[tid - 32];
    __syncthreads();

    int b = blockIdx.x*8 + w;
    float v0 = g_vs[(size_t)b*72 + lane];
    float v1 = g_vs[(size_t)b*72 + lane + 32];
    float rln = (lane < 8) ? out[OFF_ROUTER + (size_t)b*8 + lane] : 0.f;
    float zn0 = 0.f, zn1 = 0.f, zq0 = 0.f, zq1 = 0.f, lacc = 0.f;

    #pragma unroll 1
    for (int n = 0; n < NCC; n++){
        int idx = g_idx[b*NCC + n];
        const float* cr = &cb[((size_t)n*CODES + idx)*64];
        float z0 = cr[lane], z1 = cr[lane + 32];
        float d0 = v0 - z0, d1 = v1 - z1;

        float hid = sb1[lane];
        #pragma unroll
        for (int k = 0; k < 32; k++){
            float dk = __shfl_sync(0xffffffffu, d0, k);
            hid += dk * sW1[k*32 + lane];
        }
        #pragma unroll
        for (int k = 0; k < 32; k++){
            float dk = __shfl_sync(0xffffffffu, d1, k);
            hid += dk * sW1[(k + 32)*32 + lane];
        }
        float gg = 0.5f*hid*(1.0f + erff(hid*0.70710678f));
        float o0 = sb2[lane], o1 = sb2[lane + 32];
        #pragma unroll
        for (int k = 0; k < 32; k++){
            float hk = __shfl_sync(0xffffffffu, gg, k);
            o0 += hk * sW2[k*64 + lane];
            o1 += hk * sW2[k*64 + lane + 32];
        }
        size_t zb = OFF_ZNALL + ((size_t)b*NCC + n)*64;
        out[zb + lane]      = o0;
        out[zb + lane + 32] = o1;

        float rw = __shfl_sync(0xffffffffu, rln, n);
        zn0 += rw*o0; zn1 += rw*o1;          // deterministic n-ascending sum
        zq0 += rw*z0; zq1 += rw*z1;

        float dd = d0*d0 + d1*d1;
        #pragma unroll
        for (int o = 16; o > 0; o >>= 1) dd += __shfl_xor_sync(0xffffffffu, dd, o);
        lacc += rw*dd;
    }

    out[OFF_ZN   + (size_t)b*64 + lane]      = zn0;
    out[OFF_ZN   + (size_t)b*64 + lane + 32] = zn1;
    out[OFF_ZTEX + (size_t)b*64 + lane]      = v0 - zq0 - zn0;
    out[OFF_ZTEX + (size_t)b*64 + lane + 32] = v1 - zq1 - zn1;
    out[OFF_ZGEO + (size_t)b*64 + lane]      = zq0 + zn0;
    out[OFF_ZGEO + (size_t)b*64 + lane + 32] = zq1 + zn1;

    if (lane == 0) sloss[w] = lacc;
    __syncthreads();
    if (tid == 0){
        float s = 0.f;
        #pragma unroll
        for (int i = 0; i < 8; i++) s += sloss[i];
        atomicAdd(&g_loss, (double)s);
    }
}

// ---------------- K7: vq_loss = 1.25 * S / (B*L) --------------------------
__global__ void k7_loss(float* __restrict__ out){
    out[OFF_LOSS] = (float)(1.25 * g_loss / ((double)NB * (double)LL));
}

// ---------------- launch ---------------------------------------------------
extern "C" void kernel_launch(void* const* d_in, const int* in_sizes, int n_in,
                              void* d_out, int out_size){
    const float* x   = (const float*)d_in[0];
    const float* W1  = (const float*)d_in[1];
    const float* b1  = (const float*)d_in[2];
    const float* lg  = (const float*)d_in[3];
    const float* lb  = (const float*)d_in[4];
    const float* W2  = (const float*)d_in[5];
    const float* b2  = (const float*)d_in[6];
    const float* Wk  = (const float*)d_in[7];
    const float* bk  = (const float*)d_in[8];
    const float* cq  = (const float*)d_in[9];
    const float* Wv  = (const float*)d_in[10];
    const float* bv  = (const float*)d_in[11];
    const float* cb  = (const float*)d_in[12];
    const float* Ws1 = (const float*)d_in[13];
    const float* bs1 = (const float*)d_in[14];
    const float* Ws2 = (const float*)d_in[15];
    const float* bs2 = (const float*)d_in[16];
    float* out = (float*)d_out;

    k0_prep<<<25, 256>>>(Wk, bk, cq, cb);
    k1_in<<<NB/16, 256>>>(x, W1, b1, lg, lb);
    dim3 g2(HH/64, NB/128);
    k2_gemm_gelu<<<g2, 256>>>(W2, b2);
    k3_vproj<<<NB/64, 256>>>(Wv, bv);
    k4_router<<<NB/256, 256>>>(out);
    k5_vq<<<NB/32, 256>>>(cb, out);
    k6_final<<<NB/8, 256>>>(cb, Ws1, bs1, Ws2, bs2, out);
    k7_loss<<<1, 1>>>(out);
}